// round 4
// baseline (speedup 1.0000x reference)
#include <cuda_runtime.h>
#include <cuda_fp16.h>
#include <cstdint>

// Winograd F(4x4,3x3): N=16, Cin=Cout=64, H=W=128, pad=1, nt=32, T=16384.
// Round 4: fused GEMM + output transform. M stays in registers.
//
//   K0: weight (o,i,ab) fp32 -> g_Wh[ab][o][i] fp16
//   K1: input transform x -> g_Vh[ab][i][t] fp16   (t = n*1024 + p*32 + q)
//   K2: per t-block CTA: loop ab=0..35 { HMMA M_ab = W_ab * V_ab;
//         fold b: P[y] += AT[y][b]*M; } fold a: yacc[x][y] += AT[x][a]*P[y];
//       write y + bias directly. fp32 accumulation throughout.

#define TQ 16384
#define CH 64
#define ABN 36
#define VSLICE (CH * TQ)

__device__ __half g_Vh[ABN * CH * TQ];   // 75.5 MB
__device__ __half g_Wh[ABN * CH * CH];   // 288 KB (L2-resident in K2)

__device__ __forceinline__ uint32_t smem_u32(const void* p) {
    uint32_t a;
    asm("{ .reg .u64 t; cvta.to.shared.u64 t, %1; cvt.u32.u64 %0, t; }"
        : "=r"(a) : "l"(p));
    return a;
}

#define CP_ASYNC16(dst, src) \
    asm volatile("cp.async.ca.shared.global [%0], [%1], 16;" \
                 :: "r"(dst), "l"(src) : "memory")
#define CP_ASYNC8(dst, src) \
    asm volatile("cp.async.ca.shared.global [%0], [%1], 8;" \
                 :: "r"(dst), "l"(src) : "memory")
#define CP_COMMIT() asm volatile("cp.async.commit_group;" ::: "memory")
#define CP_WAIT1()  asm volatile("cp.async.wait_group 1;" ::: "memory")

// ---------------------------------------------------------------------------
// K0: weight reorder. src w[o][i][ab] fp32 -> g_Wh[ab][o][i] fp16
// ---------------------------------------------------------------------------
__global__ void k_wreorder(const float* __restrict__ w) {
    int tid = blockIdx.x * blockDim.x + threadIdx.x;
    if (tid >= ABN * CH * CH) return;
    int i  = tid & 63;
    int o  = (tid >> 6) & 63;
    int ab = tid >> 12;
    g_Wh[tid] = __float2half_rn(w[(o * 64 + i) * ABN + ab]);
}

// ---------------------------------------------------------------------------
// K1: input transform -> g_Vh[ab][c][t] fp16
// ---------------------------------------------------------------------------
__device__ __forceinline__ void bt_apply(const float d0, const float d1,
                                         const float d2, const float d3,
                                         const float d4, const float d5,
                                         float* out) {
    out[0] = 4.f * d0 - 5.f * d2 + d4;
    out[1] = -4.f * (d1 + d2) + d3 + d4;
    out[2] = 4.f * (d1 - d2) - d3 + d4;
    out[3] = -2.f * d1 - d2 + 2.f * d3 + d4;
    out[4] = 2.f * d1 - d2 - 2.f * d3 + d4;
    out[5] = 4.f * d1 - 5.f * d3 + d5;
}

__global__ __launch_bounds__(256)
void k_input_transform(const float* __restrict__ x) {
    int tid = blockIdx.x * blockDim.x + threadIdx.x;
    int q = tid & 31;
    int p = (tid >> 5) & 31;
    int c = (tid >> 10) & 63;
    int n = tid >> 16;

    const float* xp = x + (((long)n * CH + c) << 14);
    int r0 = p * 4 - 1;
    int c0 = q * 4 - 1;

    float d[6][6];
#pragma unroll
    for (int i = 0; i < 6; i++) {
        int r = r0 + i;
        bool rv = (r >= 0) && (r < 128);
        const float* row = xp + r * 128;
#pragma unroll
        for (int j = 0; j < 6; j++) {
            int cc = c0 + j;
            d[i][j] = (rv && cc >= 0 && cc < 128) ? row[cc] : 0.f;
        }
    }

    float wrow[6][6];
#pragma unroll
    for (int j = 0; j < 6; j++) {
        float t[6];
        bt_apply(d[0][j], d[1][j], d[2][j], d[3][j], d[4][j], d[5][j], t);
#pragma unroll
        for (int a = 0; a < 6; a++) wrow[a][j] = t[a];
    }

    int t = (n << 10) + (p << 5) + q;
    int base = c * TQ + t;
#pragma unroll
    for (int a = 0; a < 6; a++) {
        float v[6];
        bt_apply(wrow[a][0], wrow[a][1], wrow[a][2], wrow[a][3], wrow[a][4],
                 wrow[a][5], v);
#pragma unroll
        for (int b = 0; b < 6; b++) {
            g_Vh[(a * 6 + b) * VSLICE + base] = __float2half_rn(v[b]);
        }
    }
}

// ---------------------------------------------------------------------------
// K2: fused GEMM + output transform.
// grid = TQ/32 = 512 CTAs, block = 512 (16 warps).
// CTA tile: o=64 x t=32. Warp tile m16(o) x n8(t): wid -> o0=(wid&3)*16,
// t0=(wid>>2)*8. Per thread 4 cells, 16 y-values each (register resident).
// 3-stage cp.async pipeline over the 36 ab slices.
// ---------------------------------------------------------------------------
__global__ __launch_bounds__(512, 1)
void k_gemm_fused(const float* __restrict__ bias, float* __restrict__ y) {
    __shared__ __half Ws[3][64][72];   // [stage][o][i] +8 pad
    __shared__ __half Vs[3][64][40];   // [stage][i][t] +8 pad

    const int tid = threadIdx.x;
    const int wid = tid >> 5;
    const int lid = tid & 31;
    const int tb  = blockIdx.x * 32;

    // per-thread cp.async assignments
    const int w_o = tid >> 3;             // 0..63
    const int w_c = (tid & 7) * 8;        // 8 halves = 16B
    const int v_i = tid >> 3;             // 0..63
    const int v_t = (tid & 7) * 4;        // 4 halves = 8B

    const int o0 = (wid & 3) * 16;
    const int t0 = (wid >> 2) * 8;

    // output transform coefficients (compile-time folded via full unroll)
    const float ATm[4][6] = {{1, 1, 1, 1, 1, 0},
                             {0, 1, -1, 2, -2, 0},
                             {0, 1, 1, 4, 4, 0},
                             {0, 1, -1, 8, -8, 1}};

    float yacc[4][16];
#pragma unroll
    for (int c = 0; c < 4; c++)
#pragma unroll
        for (int k = 0; k < 16; k++) yacc[c][k] = 0.f;

    // prologue: stage ab=0 into buffer 0
    {
        CP_ASYNC16(smem_u32(&Ws[0][w_o][w_c]), g_Wh + w_o * 64 + w_c);
        CP_ASYNC8(smem_u32(&Vs[0][v_i][v_t]),
                  g_Vh + (size_t)v_i * TQ + tb + v_t);
        CP_COMMIT();
    }

#pragma unroll
    for (int a = 0; a < 6; a++) {
        float P[4][4];
#pragma unroll
        for (int c = 0; c < 4; c++)
#pragma unroll
            for (int yy = 0; yy < 4; yy++) P[c][yy] = 0.f;

#pragma unroll
        for (int b = 0; b < 6; b++) {
            const int ab = a * 6 + b;
            // prefetch ab+1 into stage (ab+1)%3
            if (ab + 1 < ABN) {
                const int s1 = (ab + 1) % 3;
                CP_ASYNC16(smem_u32(&Ws[s1][w_o][w_c]),
                           g_Wh + (ab + 1) * (CH * CH) + w_o * 64 + w_c);
                CP_ASYNC8(smem_u32(&Vs[s1][v_i][v_t]),
                          g_Vh + (size_t)(ab + 1) * VSLICE +
                              (size_t)v_i * TQ + tb + v_t);
            }
            CP_COMMIT();
            CP_WAIT1();
            __syncthreads();

            const int s = ab % 3;
            float mc[4] = {0.f, 0.f, 0.f, 0.f};
#pragma unroll
            for (int ks = 0; ks < 4; ks++) {
                uint32_t a0, a1, a2, a3, b0, b1;
                uint32_t aaddr = smem_u32(
                    &Ws[s][o0 + (lid & 15)][ks * 16 + ((lid >> 4) & 1) * 8]);
                asm volatile(
                    "ldmatrix.sync.aligned.m8n8.x4.shared.b16 "
                    "{%0,%1,%2,%3}, [%4];"
                    : "=r"(a0), "=r"(a1), "=r"(a2), "=r"(a3)
                    : "r"(aaddr));
                uint32_t baddr = smem_u32(&Vs[s][ks * 16 + (lid & 15)][t0]);
                asm volatile(
                    "ldmatrix.sync.aligned.m8n8.x2.trans.shared.b16 "
                    "{%0,%1}, [%2];"
                    : "=r"(b0), "=r"(b1)
                    : "r"(baddr));
                asm volatile(
                    "mma.sync.aligned.m16n8k16.row.col.f32.f16.f16.f32 "
                    "{%0,%1,%2,%3}, {%4,%5,%6,%7}, {%8,%9}, {%0,%1,%2,%3};"
                    : "+f"(mc[0]), "+f"(mc[1]), "+f"(mc[2]), "+f"(mc[3])
                    : "r"(a0), "r"(a1), "r"(a2), "r"(a3), "r"(b0), "r"(b1));
            }

            // __syncthreads before next stage-overwrite is the loop-top one;
            // with 3 stages the buffer written at iter ab+1 was last read at
            // iter ab-2, whose consumers all passed the iter ab-1 barrier.

            // fold b: P[c][y] += AT[y][b] * M (skip structural zeros)
#pragma unroll
            for (int yy = 0; yy < 4; yy++) {
                if (ATm[yy][b] != 0.f) {
                    const float cf = ATm[yy][b];
#pragma unroll
                    for (int c = 0; c < 4; c++) P[c][yy] += cf * mc[c];
                }
            }
        }

        // fold a: yacc[c][x][y] += AT[x][a] * P[c][y]
#pragma unroll
        for (int xx = 0; xx < 4; xx++) {
            if (ATm[xx][a] != 0.f) {
                const float cf = ATm[xx][a];
#pragma unroll
                for (int c = 0; c < 4; c++)
#pragma unroll
                    for (int yy = 0; yy < 4; yy++)
                        yacc[c][xx * 4 + yy] += cf * P[c][yy];
            }
        }
    }

    // epilogue: bias + store. cell c: o = o0+(lid>>2)+(c>>1)*8,
    //                                t = tb+t0+(lid&3)*2+(c&1)
#pragma unroll
    for (int c = 0; c < 4; c++) {
        int o = o0 + (lid >> 2) + (c >> 1) * 8;
        int t = tb + t0 + (lid & 3) * 2 + (c & 1);
        int n = t >> 10;
        int p = (t >> 5) & 31;
        int q = t & 31;
        float bv = bias[o];
        float* yp = y + (((size_t)n * CH + o) << 14) + (p * 4) * 128 + q * 4;
#pragma unroll
        for (int xx = 0; xx < 4; xx++) {
            float4 v = make_float4(yacc[c][xx * 4 + 0] + bv,
                                   yacc[c][xx * 4 + 1] + bv,
                                   yacc[c][xx * 4 + 2] + bv,
                                   yacc[c][xx * 4 + 3] + bv);
            *(float4*)(yp + xx * 128) = v;
        }
    }
}

// ---------------------------------------------------------------------------
extern "C" void kernel_launch(void* const* d_in, const int* in_sizes, int n_in,
                              void* d_out, int out_size) {
    const float* x    = (const float*)d_in[0];
    const float* w    = (const float*)d_in[1];
    const float* bias = (const float*)d_in[2];
    float* y = (float*)d_out;

    k_wreorder<<<(ABN * CH * CH + 255) / 256, 256>>>(w);
    k_input_transform<<<4096, 256>>>(x);
    k_gemm_fused<<<TQ / 32, 512>>>(bias, y);
}

// round 5
// speedup vs baseline: 1.2274x; 1.2274x over previous
#include <cuda_runtime.h>
#include <cuda_fp16.h>
#include <cstdint>

// Winograd F(4x4,3x3): N=16, Cin=Cout=64, H=W=128, pad=1, nt=32, T=16384.
// Round 5: fused GEMM + output transform, blocked V layout, depth-2 pipeline.
//
//   K0: weight (o,i,ab) fp32 -> g_Wh[ab][o][i] fp16  (smem-transposed, coalesced)
//   K1: input transform x -> g_Vh[tblk][ab][i][32] fp16 (blocked: 4KB/stage chunk)
//   K2: CTA = 32(o) x 32(t), loops ab=0..35: HMMA + factorized AT folds,
//       y written directly with bias. fp32 accumulation. M never hits gmem.

#define TQ 16384
#define CH 64
#define ABN 36

__device__ __half g_Vh[ABN * CH * TQ];   // 75.5 MB, blocked layout
__device__ __half g_Wh[ABN * CH * CH];   // 288 KB (L2-resident in K2)

__device__ __forceinline__ uint32_t smem_u32(const void* p) {
    uint32_t a;
    asm("{ .reg .u64 t; cvta.to.shared.u64 t, %1; cvt.u32.u64 %0, t; }"
        : "=r"(a) : "l"(p));
    return a;
}

#define CP_ASYNC16(dst, src) \
    asm volatile("cp.async.ca.shared.global [%0], [%1], 16;" \
                 :: "r"(dst), "l"(src) : "memory")
#define CP_COMMIT() asm volatile("cp.async.commit_group;" ::: "memory")
#define CP_WAIT2()  asm volatile("cp.async.wait_group 2;" ::: "memory")

// ---------------------------------------------------------------------------
// K0: weight reorder. src w[o][i][ab] fp32 -> g_Wh[ab][o][i] fp16.
// One block per o: reads 2304 floats contiguous, writes 36 chunks of 128 B.
// ---------------------------------------------------------------------------
__global__ __launch_bounds__(256)
void k_wreorder(const float* __restrict__ w) {
    __shared__ float s[CH * ABN];   // 2304
    const int o = blockIdx.x;
    const float* src = w + o * (CH * ABN);
    for (int k = threadIdx.x; k < CH * ABN; k += 256) s[k] = src[k];
    __syncthreads();
    for (int k = threadIdx.x; k < CH * ABN; k += 256) {
        int ab = k >> 6;
        int i  = k & 63;
        g_Wh[ab * (CH * CH) + o * CH + i] = __float2half_rn(s[i * ABN + ab]);
    }
}

// ---------------------------------------------------------------------------
// K1: input transform -> blocked V. t = n*1024 + p*32 + q; tblk = t>>5.
// ---------------------------------------------------------------------------
__device__ __forceinline__ void bt_apply(const float d0, const float d1,
                                         const float d2, const float d3,
                                         const float d4, const float d5,
                                         float* out) {
    out[0] = 4.f * d0 - 5.f * d2 + d4;
    out[1] = -4.f * (d1 + d2) + d3 + d4;
    out[2] = 4.f * (d1 - d2) - d3 + d4;
    out[3] = -2.f * d1 - d2 + 2.f * d3 + d4;
    out[4] = 2.f * d1 - d2 - 2.f * d3 + d4;
    out[5] = 4.f * d1 - 5.f * d3 + d5;
}

__global__ __launch_bounds__(256)
void k_input_transform(const float* __restrict__ x) {
    int tid = blockIdx.x * blockDim.x + threadIdx.x;
    int q = tid & 31;
    int p = (tid >> 5) & 31;
    int c = (tid >> 10) & 63;
    int n = tid >> 16;

    const float* xp = x + (((long)n * CH + c) << 14);
    int r0 = p * 4 - 1;
    int c0 = q * 4 - 1;

    float d[6][6];
#pragma unroll
    for (int i = 0; i < 6; i++) {
        int r = r0 + i;
        bool rv = (r >= 0) && (r < 128);
        const float* row = xp + r * 128;
#pragma unroll
        for (int j = 0; j < 6; j++) {
            int cc = c0 + j;
            d[i][j] = (rv && cc >= 0 && cc < 128) ? row[cc] : 0.f;
        }
    }

    float wrow[6][6];
#pragma unroll
    for (int j = 0; j < 6; j++) {
        float t[6];
        bt_apply(d[0][j], d[1][j], d[2][j], d[3][j], d[4][j], d[5][j], t);
#pragma unroll
        for (int a = 0; a < 6; a++) wrow[a][j] = t[a];
    }

    int tblk = (n << 5) + p;
    __half* vdst = g_Vh + ((size_t)tblk * ABN) * 2048 + c * 32 + q;
#pragma unroll
    for (int a = 0; a < 6; a++) {
        float v[6];
        bt_apply(wrow[a][0], wrow[a][1], wrow[a][2], wrow[a][3], wrow[a][4],
                 wrow[a][5], v);
#pragma unroll
        for (int b = 0; b < 6; b++) {
            vdst[(a * 6 + b) * 2048] = __float2half_rn(v[b]);
        }
    }
}

// ---------------------------------------------------------------------------
// K2: fused GEMM + output transform.
// grid = (TQ/32, 2), block = 256 (8 warps), 2 CTAs/SM.
// CTA tile: o=32 (half, by blockIdx.y) x t=32. Warp m16(o) x n8(t):
//   o0=(wid&1)*16, t0=(wid>>1)*8. 4 cells/thread, 16 y-vals each.
// 4-stage cp.async pipeline, prefetch distance 2 (wait_group 2).
// Per stage: W chunk 4KB (32x64, L2-hit) + V chunk 4KB (contiguous, blocked).
// ---------------------------------------------------------------------------
__global__ __launch_bounds__(256, 2)
void k_gemm_fused(const float* __restrict__ bias, float* __restrict__ y) {
    __shared__ __half Ws[4][32][72];   // [stage][o][i], row 144B (phase-conflict-free)
    __shared__ __half Vs[4][64][40];   // [stage][i][t], row 80B  (phase-conflict-free)

    const int tid = threadIdx.x;
    const int wid = tid >> 5;
    const int lid = tid & 31;
    const int tblk = blockIdx.x;
    const int oh   = blockIdx.y;      // o half: 0 or 1
    const int tb   = tblk * 32;

    const __half* Wsrc = g_Wh + oh * 2048 + (size_t)tid * 8;     // + ab*4096
    const __half* Vsrc = g_Vh + (size_t)tblk * ABN * 2048 + (size_t)tid * 8;

    const uint32_t wdst0 = smem_u32(&Ws[0][tid >> 3][(tid & 7) * 8]);
    const uint32_t vdst0 = smem_u32(&Vs[0][tid >> 2][(tid & 3) * 8]);
    const uint32_t WSTG = 32 * 72 * 2;   // 4608 B per stage
    const uint32_t VSTG = 64 * 40 * 2;   // 5120 B per stage

    const int o0 = (wid & 1) * 16;
    const int t0 = (wid >> 1) * 8;

    const float ATm[4][6] = {{1, 1, 1, 1, 1, 0},
                             {0, 1, -1, 2, -2, 0},
                             {0, 1, 1, 4, 4, 0},
                             {0, 1, -1, 8, -8, 1}};

    float yacc[4][16];
#pragma unroll
    for (int c = 0; c < 4; c++)
#pragma unroll
        for (int k = 0; k < 16; k++) yacc[c][k] = 0.f;

    // prologue: stage ab=0,1 into buffers 0,1 (one group each)
#pragma unroll
    for (int ab = 0; ab < 2; ab++) {
        CP_ASYNC16(wdst0 + ab * WSTG, Wsrc + ab * 4096);
        CP_ASYNC16(vdst0 + ab * VSTG, Vsrc + ab * 2048);
        CP_COMMIT();
    }

#pragma unroll
    for (int a = 0; a < 6; a++) {
        float P[4][4];
#pragma unroll
        for (int c = 0; c < 4; c++)
#pragma unroll
            for (int yy = 0; yy < 4; yy++) P[c][yy] = 0.f;

#pragma unroll
        for (int b = 0; b < 6; b++) {
            const int ab = a * 6 + b;
            // prefetch ab+2 into buffer (ab+2)&3; commit every iter so
            // group index tracks ab. Buffer safety: its last readers ran at
            // iter ab-2 and everyone passed sync(ab-1).
            if (ab + 2 < ABN) {
                const int s2 = (ab + 2) & 3;
                CP_ASYNC16(wdst0 + s2 * WSTG, Wsrc + (size_t)(ab + 2) * 4096);
                CP_ASYNC16(vdst0 + s2 * VSTG, Vsrc + (size_t)(ab + 2) * 2048);
            }
            CP_COMMIT();
            CP_WAIT2();          // group for ab complete
            __syncthreads();

            const int s = ab & 3;
            float mc[4] = {0.f, 0.f, 0.f, 0.f};
#pragma unroll
            for (int ks = 0; ks < 4; ks++) {
                uint32_t a0, a1, a2, a3, b0, b1;
                uint32_t aaddr = smem_u32(
                    &Ws[s][o0 + (lid & 15)][ks * 16 + ((lid >> 4) & 1) * 8]);
                asm volatile(
                    "ldmatrix.sync.aligned.m8n8.x4.shared.b16 "
                    "{%0,%1,%2,%3}, [%4];"
                    : "=r"(a0), "=r"(a1), "=r"(a2), "=r"(a3)
                    : "r"(aaddr));
                uint32_t baddr = smem_u32(&Vs[s][ks * 16 + (lid & 15)][t0]);
                asm volatile(
                    "ldmatrix.sync.aligned.m8n8.x2.trans.shared.b16 "
                    "{%0,%1}, [%2];"
                    : "=r"(b0), "=r"(b1)
                    : "r"(baddr));
                asm volatile(
                    "mma.sync.aligned.m16n8k16.row.col.f32.f16.f16.f32 "
                    "{%0,%1,%2,%3}, {%4,%5,%6,%7}, {%8,%9}, {%0,%1,%2,%3};"
                    : "+f"(mc[0]), "+f"(mc[1]), "+f"(mc[2]), "+f"(mc[3])
                    : "r"(a0), "r"(a1), "r"(a2), "r"(a3), "r"(b0), "r"(b1));
            }

            // fold b: P[c][y] += AT[y][b] * M (structural zeros skipped)
#pragma unroll
            for (int yy = 0; yy < 4; yy++) {
                if (ATm[yy][b] != 0.f) {
                    const float cf = ATm[yy][b];
#pragma unroll
                    for (int c = 0; c < 4; c++) P[c][yy] += cf * mc[c];
                }
            }
        }

        // fold a: yacc[c][x*4+y] += AT[x][a] * P[c][y]
#pragma unroll
        for (int xx = 0; xx < 4; xx++) {
            if (ATm[xx][a] != 0.f) {
                const float cf = ATm[xx][a];
#pragma unroll
                for (int c = 0; c < 4; c++)
#pragma unroll
                    for (int yy = 0; yy < 4; yy++)
                        yacc[c][xx * 4 + yy] += cf * P[c][yy];
            }
        }
    }

    // epilogue: bias + store.
    // cell c: o = oh*32 + o0 + (lid>>2) + (c>>1)*8, t = tb+t0+(lid&3)*2+(c&1)
#pragma unroll
    for (int c = 0; c < 4; c++) {
        int o = oh * 32 + o0 + (lid >> 2) + ((c >> 1) << 3);
        int t = tb + t0 + ((lid & 3) << 1) + (c & 1);
        int n = t >> 10;
        int p = (t >> 5) & 31;
        int q = t & 31;
        float bv = bias[o];
        float* yp = y + (((size_t)n * CH + o) << 14) + (p * 4) * 128 + q * 4;
#pragma unroll
        for (int xx = 0; xx < 4; xx++) {
            float4 v = make_float4(yacc[c][xx * 4 + 0] + bv,
                                   yacc[c][xx * 4 + 1] + bv,
                                   yacc[c][xx * 4 + 2] + bv,
                                   yacc[c][xx * 4 + 3] + bv);
            *(float4*)(yp + xx * 128) = v;
        }
    }
}

// ---------------------------------------------------------------------------
extern "C" void kernel_launch(void* const* d_in, const int* in_sizes, int n_in,
                              void* d_out, int out_size) {
    const float* x    = (const float*)d_in[0];
    const float* w    = (const float*)d_in[1];
    const float* bias = (const float*)d_in[2];
    float* y = (float*)d_out;

    k_wreorder<<<CH, 256>>>(w);
    k_input_transform<<<4096, 256>>>(x);
    dim3 g2(TQ / 32, 2);
    k_gemm_fused<<<g2, 256>>>(bias, y);
}

// round 6
// speedup vs baseline: 1.2483x; 1.0170x over previous
#include <cuda_runtime.h>
#include <cuda_fp16.h>
#include <cstdint>

// Winograd F(4x4,3x3): N=16, Cin=Cout=64, H=W=128, pad=1, nt=32, T=16384.
// Round 6: fused GEMM + output transform, blocked V, distance-4 cp.async
// pipeline with 5 smem buffers.
//
//   K0: weight (o,i,ab) fp32 -> g_Wh[ab][o][i] fp16
//   K1: input transform x -> g_Vh[tblk][ab][i][32] fp16 (4KB/stage chunk)
//   K2: CTA = 32(o) x 32(t), ab=0..35 stages: HMMA + factorized AT folds,
//       y written directly with bias. fp32 accumulation; M never hits gmem.

#define TQ 16384
#define CH 64
#define ABN 36

__device__ __half g_Vh[ABN * CH * TQ];   // 75.5 MB, blocked layout
__device__ __half g_Wh[ABN * CH * CH];   // 288 KB (L2-resident in K2)

__device__ __forceinline__ uint32_t smem_u32(const void* p) {
    uint32_t a;
    asm("{ .reg .u64 t; cvta.to.shared.u64 t, %1; cvt.u32.u64 %0, t; }"
        : "=r"(a) : "l"(p));
    return a;
}

#define CP_ASYNC16(dst, src) \
    asm volatile("cp.async.ca.shared.global [%0], [%1], 16;" \
                 :: "r"(dst), "l"(src) : "memory")
#define CP_COMMIT() asm volatile("cp.async.commit_group;" ::: "memory")
#define CP_WAIT3()  asm volatile("cp.async.wait_group 3;" ::: "memory")

// ---------------------------------------------------------------------------
// K0: weight reorder. src w[o][i][ab] fp32 -> g_Wh[ab][o][i] fp16.
// Coalesced read, scattered 2B writes (1.2MB total; latency-bound, ~4.7us).
// ---------------------------------------------------------------------------
__global__ void k_wreorder(const float* __restrict__ w) {
    int tid = blockIdx.x * blockDim.x + threadIdx.x;
    if (tid >= ABN * CH * CH) return;
    int ab = tid % ABN;
    int i  = (tid / ABN) % CH;
    int o  = tid / (ABN * CH);
    g_Wh[ab * (CH * CH) + o * CH + i] = __float2half_rn(w[tid]);
}

// ---------------------------------------------------------------------------
// K1: input transform -> blocked V. t = n*1024 + p*32 + q; tblk = t>>5.
// ---------------------------------------------------------------------------
__device__ __forceinline__ void bt_apply(const float d0, const float d1,
                                         const float d2, const float d3,
                                         const float d4, const float d5,
                                         float* out) {
    out[0] = 4.f * d0 - 5.f * d2 + d4;
    out[1] = -4.f * (d1 + d2) + d3 + d4;
    out[2] = 4.f * (d1 - d2) - d3 + d4;
    out[3] = -2.f * d1 - d2 + 2.f * d3 + d4;
    out[4] = 2.f * d1 - d2 - 2.f * d3 + d4;
    out[5] = 4.f * d1 - 5.f * d3 + d5;
}

__global__ __launch_bounds__(256)
void k_input_transform(const float* __restrict__ x) {
    int tid = blockIdx.x * blockDim.x + threadIdx.x;
    int q = tid & 31;
    int p = (tid >> 5) & 31;
    int c = (tid >> 10) & 63;
    int n = tid >> 16;

    const float* xp = x + (((long)n * CH + c) << 14);
    int r0 = p * 4 - 1;
    int c0 = q * 4 - 1;

    float d[6][6];
#pragma unroll
    for (int i = 0; i < 6; i++) {
        int r = r0 + i;
        bool rv = (r >= 0) && (r < 128);
        const float* row = xp + r * 128;
#pragma unroll
        for (int j = 0; j < 6; j++) {
            int cc = c0 + j;
            d[i][j] = (rv && cc >= 0 && cc < 128) ? row[cc] : 0.f;
        }
    }

    float wrow[6][6];
#pragma unroll
    for (int j = 0; j < 6; j++) {
        float t[6];
        bt_apply(d[0][j], d[1][j], d[2][j], d[3][j], d[4][j], d[5][j], t);
#pragma unroll
        for (int a = 0; a < 6; a++) wrow[a][j] = t[a];
    }

    int tblk = (n << 5) + p;
    __half* vdst = g_Vh + ((size_t)tblk * ABN) * 2048 + c * 32 + q;
#pragma unroll
    for (int a = 0; a < 6; a++) {
        float v[6];
        bt_apply(wrow[a][0], wrow[a][1], wrow[a][2], wrow[a][3], wrow[a][4],
                 wrow[a][5], v);
#pragma unroll
        for (int b = 0; b < 6; b++) {
            vdst[(a * 6 + b) * 2048] = __float2half_rn(v[b]);
        }
    }
}

// ---------------------------------------------------------------------------
// K2: fused GEMM + output transform.
// grid = (TQ/32, 2), block = 256 (8 warps), 2 CTAs/SM.
// CTA tile: o=32 (half via blockIdx.y) x t=32. Warp m16(o) x n8(t).
// 5-buffer cp.async pipeline, prefetch distance 4.
// Loop body order: wait -> sync -> issue(ab+4) -> commit -> compute.
//   (issue after sync makes writing buffer (ab+4)%5 == (ab-1)%5 safe: its
//    last readers ran at iter ab-1, ordered before sync(ab).)
// Wait count: prologue commits 4 groups (ab=0..3); before iter ab's commit
// the newest committed group is ab+3, so wait_group 3 completes group ab.
// ---------------------------------------------------------------------------
__global__ __launch_bounds__(256, 2)
void k_gemm_fused(const float* __restrict__ bias, float* __restrict__ y) {
    __shared__ __half Ws[5][32][72];   // [stage][o][i]
    __shared__ __half Vs[5][64][40];   // [stage][i][t]

    const int tid = threadIdx.x;
    const int wid = tid >> 5;
    const int lid = tid & 31;
    const int tblk = blockIdx.x;
    const int oh   = blockIdx.y;
    const int tb   = tblk * 32;

    const __half* Wsrc = g_Wh + oh * 2048 + (size_t)tid * 8;   // + ab*4096
    const __half* Vsrc = g_Vh + (size_t)tblk * ABN * 2048 + (size_t)tid * 8;

    const uint32_t wdst0 = smem_u32(&Ws[0][tid >> 3][(tid & 7) * 8]);
    const uint32_t vdst0 = smem_u32(&Vs[0][tid >> 2][(tid & 3) * 8]);
    const uint32_t WSTG = 32 * 72 * 2;   // 4608 B
    const uint32_t VSTG = 64 * 40 * 2;   // 5120 B

    const int o0 = (wid & 1) * 16;
    const int t0 = (wid >> 1) * 8;

    const float ATm[4][6] = {{1, 1, 1, 1, 1, 0},
                             {0, 1, -1, 2, -2, 0},
                             {0, 1, 1, 4, 4, 0},
                             {0, 1, -1, 8, -8, 1}};

    float yacc[4][16];
#pragma unroll
    for (int c = 0; c < 4; c++)
#pragma unroll
        for (int k = 0; k < 16; k++) yacc[c][k] = 0.f;

    // prologue: stage ab=0..3 into buffers 0..3, one commit group each.
#pragma unroll
    for (int ab = 0; ab < 4; ab++) {
        CP_ASYNC16(wdst0 + ab * WSTG, Wsrc + ab * 4096);
        CP_ASYNC16(vdst0 + ab * VSTG, Vsrc + ab * 2048);
        CP_COMMIT();
    }

#pragma unroll
    for (int a = 0; a < 6; a++) {
        float P[4][4];
#pragma unroll
        for (int c = 0; c < 4; c++)
#pragma unroll
            for (int yy = 0; yy < 4; yy++) P[c][yy] = 0.f;

#pragma unroll
        for (int b = 0; b < 6; b++) {
            const int ab = a * 6 + b;     // compile-time const (full unroll)
            const int s  = ab % 5;

            CP_WAIT3();                   // group ab landed
            __syncthreads();

            if (ab + 4 < ABN) {
                const int s4 = (ab + 4) % 5;
                CP_ASYNC16(wdst0 + s4 * WSTG, Wsrc + (size_t)(ab + 4) * 4096);
                CP_ASYNC16(vdst0 + s4 * VSTG, Vsrc + (size_t)(ab + 4) * 2048);
            }
            CP_COMMIT();

            float mc[4] = {0.f, 0.f, 0.f, 0.f};
#pragma unroll
            for (int ks = 0; ks < 4; ks++) {
                uint32_t a0, a1, a2, a3, b0, b1;
                uint32_t aaddr = smem_u32(
                    &Ws[s][o0 + (lid & 15)][ks * 16 + ((lid >> 4) & 1) * 8]);
                asm volatile(
                    "ldmatrix.sync.aligned.m8n8.x4.shared.b16 "
                    "{%0,%1,%2,%3}, [%4];"
                    : "=r"(a0), "=r"(a1), "=r"(a2), "=r"(a3)
                    : "r"(aaddr));
                uint32_t baddr = smem_u32(&Vs[s][ks * 16 + (lid & 15)][t0]);
                asm volatile(
                    "ldmatrix.sync.aligned.m8n8.x2.trans.shared.b16 "
                    "{%0,%1}, [%2];"
                    : "=r"(b0), "=r"(b1)
                    : "r"(baddr));
                asm volatile(
                    "mma.sync.aligned.m16n8k16.row.col.f32.f16.f16.f32 "
                    "{%0,%1,%2,%3}, {%4,%5,%6,%7}, {%8,%9}, {%0,%1,%2,%3};"
                    : "+f"(mc[0]), "+f"(mc[1]), "+f"(mc[2]), "+f"(mc[3])
                    : "r"(a0), "r"(a1), "r"(a2), "r"(a3), "r"(b0), "r"(b1));
            }

            // fold b: P[c][y] += AT[y][b] * M (structural zeros skipped)
#pragma unroll
            for (int yy = 0; yy < 4; yy++) {
                if (ATm[yy][b] != 0.f) {
                    const float cf = ATm[yy][b];
#pragma unroll
                    for (int c = 0; c < 4; c++) P[c][yy] += cf * mc[c];
                }
            }
        }

        // fold a: yacc[c][x*4+y] += AT[x][a] * P[c][y]
#pragma unroll
        for (int xx = 0; xx < 4; xx++) {
            if (ATm[xx][a] != 0.f) {
                const float cf = ATm[xx][a];
#pragma unroll
                for (int c = 0; c < 4; c++)
#pragma unroll
                    for (int yy = 0; yy < 4; yy++)
                        yacc[c][xx * 4 + yy] += cf * P[c][yy];
            }
        }
    }

    // epilogue: bias + store.
#pragma unroll
    for (int c = 0; c < 4; c++) {
        int o = oh * 32 + o0 + (lid >> 2) + ((c >> 1) << 3);
        int t = tb + t0 + ((lid & 3) << 1) + (c & 1);
        int n = t >> 10;
        int p = (t >> 5) & 31;
        int q = t & 31;
        float bv = bias[o];
        float* yp = y + (((size_t)n * CH + o) << 14) + (p * 4) * 128 + q * 4;
#pragma unroll
        for (int xx = 0; xx < 4; xx++) {
            float4 v = make_float4(yacc[c][xx * 4 + 0] + bv,
                                   yacc[c][xx * 4 + 1] + bv,
                                   yacc[c][xx * 4 + 2] + bv,
                                   yacc[c][xx * 4 + 3] + bv);
            *(float4*)(yp + xx * 128) = v;
        }
    }
}

// ---------------------------------------------------------------------------
extern "C" void kernel_launch(void* const* d_in, const int* in_sizes, int n_in,
                              void* d_out, int out_size) {
    const float* x    = (const float*)d_in[0];
    const float* w    = (const float*)d_in[1];
    const float* bias = (const float*)d_in[2];
    float* y = (float*)d_out;

    k_wreorder<<<(ABN * CH * CH + 255) / 256, 256>>>(w);
    k_input_transform<<<4096, 256>>>(x);
    dim3 g2(TQ / 32, 2);
    k_gemm_fused<<<g2, 256>>>(bias, y);
}

// round 7
// speedup vs baseline: 1.3837x; 1.1085x over previous
#include <cuda_runtime.h>
#include <cuda_fp16.h>
#include <cstdint>

// Winograd F(4x4,3x3): N=16, Cin=Cout=64, H=W=128, pad=1, nt=32, T=16384.
// Round 7: proven 3-kernel HMMA pipeline (r3) + coalesced K0 + half2 K3.
//
//   K0: weight (o,i,ab) fp32 -> g_Wh[ab][o][i] fp16 (half2-coalesced writes)
//   K1: input transform x -> g_Vh[ab][i][t] fp16   (t = n*1024 + p*32 + q)
//   K2: HMMA: M[ab][o][t] = sum_i W[o][i] * V[i][t] -> g_Mh fp16
//   K3: output transform, 2 t per thread via half2, + bias -> y fp32

#define TQ 16384
#define CH 64
#define ABN 36
#define VSLICE (CH * TQ)

__device__ __half g_Vh[ABN * CH * TQ];   // 75.5 MB
__device__ __half g_Mh[ABN * CH * TQ];   // 75.5 MB
__device__ __half g_Wh[ABN * CH * CH];

__device__ __forceinline__ uint32_t smem_u32(const void* p) {
    uint32_t a;
    asm("{ .reg .u64 t; cvta.to.shared.u64 t, %1; cvt.u32.u64 %0, t; }"
        : "=r"(a) : "l"(p));
    return a;
}

// ---------------------------------------------------------------------------
// K0: weight reorder. src w[o][i][ab] fp32 -> g_Wh[ab][o][i] fp16.
// Thread = (ab, o, i-pair): strided 4B reads (L2-amortized), coalesced
// half2 writes.
// ---------------------------------------------------------------------------
__global__ void k_wreorder(const float* __restrict__ w) {
    int tid = blockIdx.x * blockDim.x + threadIdx.x;
    if (tid >= ABN * CH * 32) return;
    int i2 = tid & 31;
    int o  = (tid >> 5) & 63;
    int ab = tid >> 11;
    float a0 = w[(o * 64 + i2 * 2) * ABN + ab];
    float a1 = w[(o * 64 + i2 * 2 + 1) * ABN + ab];
    *(__half2*)(g_Wh + ab * (CH * CH) + o * CH + i2 * 2) =
        __floats2half2_rn(a0, a1);
}

// ---------------------------------------------------------------------------
// K1: input transform -> g_Vh[ab][c][t] fp16
// ---------------------------------------------------------------------------
__device__ __forceinline__ void bt_apply(const float d0, const float d1,
                                         const float d2, const float d3,
                                         const float d4, const float d5,
                                         float* out) {
    out[0] = 4.f * d0 - 5.f * d2 + d4;
    out[1] = -4.f * (d1 + d2) + d3 + d4;
    out[2] = 4.f * (d1 - d2) - d3 + d4;
    out[3] = -2.f * d1 - d2 + 2.f * d3 + d4;
    out[4] = 2.f * d1 - d2 - 2.f * d3 + d4;
    out[5] = 4.f * d1 - 5.f * d3 + d5;
}

__global__ __launch_bounds__(256)
void k_input_transform(const float* __restrict__ x) {
    int tid = blockIdx.x * blockDim.x + threadIdx.x;
    int q = tid & 31;
    int p = (tid >> 5) & 31;
    int c = (tid >> 10) & 63;
    int n = tid >> 16;

    const float* xp = x + (((long)n * CH + c) << 14);
    int r0 = p * 4 - 1;
    int c0 = q * 4 - 1;

    float d[6][6];
#pragma unroll
    for (int i = 0; i < 6; i++) {
        int r = r0 + i;
        bool rv = (r >= 0) && (r < 128);
        const float* row = xp + r * 128;
#pragma unroll
        for (int j = 0; j < 6; j++) {
            int cc = c0 + j;
            d[i][j] = (rv && cc >= 0 && cc < 128) ? row[cc] : 0.f;
        }
    }

    float wrow[6][6];
#pragma unroll
    for (int j = 0; j < 6; j++) {
        float t[6];
        bt_apply(d[0][j], d[1][j], d[2][j], d[3][j], d[4][j], d[5][j], t);
#pragma unroll
        for (int a = 0; a < 6; a++) wrow[a][j] = t[a];
    }

    int t = (n << 10) + (p << 5) + q;
    int base = c * TQ + t;
#pragma unroll
    for (int a = 0; a < 6; a++) {
        float v[6];
        bt_apply(wrow[a][0], wrow[a][1], wrow[a][2], wrow[a][3], wrow[a][4],
                 wrow[a][5], v);
#pragma unroll
        for (int b = 0; b < 6; b++) {
            g_Vh[(a * 6 + b) * VSLICE + base] = __float2half_rn(v[b]);
        }
    }
}

// ---------------------------------------------------------------------------
// K2: HMMA GEMM. grid = (TQ/256, 36), block = 256 (8 warps).
// CTA tile: o=64, t=256, K=64 (resident).
// Warp tile: 32(o) x 64(t): 2 m16 x 8 n8 mma fragments, 4 k16 steps.
// ---------------------------------------------------------------------------
__global__ __launch_bounds__(256, 2)
void k_gemm_hmma() {
    __shared__ __half Ws[64][72];    // [o][i], +8 pad
    __shared__ __half Vs[64][264];   // [i][t], +8 pad

    const int tid = threadIdx.x;
    const int wid = tid >> 5;
    const int lid = tid & 31;
    const int ab = blockIdx.y;
    const int tb = blockIdx.x * 256;

    // Load W tile: 64x64 fp16 = 512 uint4.
    {
        const uint4* Wp = (const uint4*)(g_Wh + ab * (CH * CH));
#pragma unroll
        for (int it = 0; it < 2; it++) {
            int idx = tid + it * 256;
            int r = idx >> 3, c = idx & 7;
            *(uint4*)&Ws[r][c * 8] = Wp[idx];
        }
    }
    // Load V tile: 64 rows x 256 t fp16 = 2048 uint4.
    {
        const __half* Vp = g_Vh + ab * VSLICE + tb;
#pragma unroll
        for (int it = 0; it < 8; it++) {
            int idx = tid + it * 256;
            int r = idx >> 5, c = idx & 31;
            *(uint4*)&Vs[r][c * 8] =
                *(const uint4*)(Vp + (size_t)r * TQ + c * 8);
        }
    }
    __syncthreads();

    const int o0  = (wid & 1) * 32;
    const int t0w = (wid >> 1) * 64;

    float acc[2][8][4];
#pragma unroll
    for (int mi = 0; mi < 2; mi++)
#pragma unroll
        for (int nj = 0; nj < 8; nj++)
#pragma unroll
            for (int r = 0; r < 4; r++) acc[mi][nj][r] = 0.f;

#pragma unroll
    for (int ks = 0; ks < 4; ks++) {
        const int k0 = ks * 16;

        uint32_t ra[2][4];
#pragma unroll
        for (int mi = 0; mi < 2; mi++) {
            int row = o0 + mi * 16 + (lid & 7) + ((lid >> 3) & 1) * 8;
            int col = k0 + (lid >> 4) * 8;
            uint32_t addr = smem_u32(&Ws[row][col]);
            asm volatile(
                "ldmatrix.sync.aligned.m8n8.x4.shared.b16 {%0,%1,%2,%3}, [%4];"
                : "=r"(ra[mi][0]), "=r"(ra[mi][1]), "=r"(ra[mi][2]),
                  "=r"(ra[mi][3])
                : "r"(addr));
        }
        uint32_t rb[8][2];
#pragma unroll
        for (int njp = 0; njp < 4; njp++) {
            int row = k0 + (lid & 7) + ((lid >> 3) & 1) * 8;
            int col = t0w + njp * 16 + (lid >> 4) * 8;
            uint32_t addr = smem_u32(&Vs[row][col]);
            uint32_t r0, r1, r2, r3;
            asm volatile(
                "ldmatrix.sync.aligned.m8n8.x4.trans.shared.b16 {%0,%1,%2,%3}, [%4];"
                : "=r"(r0), "=r"(r1), "=r"(r2), "=r"(r3)
                : "r"(addr));
            rb[njp * 2][0] = r0; rb[njp * 2][1] = r1;
            rb[njp * 2 + 1][0] = r2; rb[njp * 2 + 1][1] = r3;
        }

#pragma unroll
        for (int mi = 0; mi < 2; mi++)
#pragma unroll
            for (int nj = 0; nj < 8; nj++) {
                asm volatile(
                    "mma.sync.aligned.m16n8k16.row.col.f32.f16.f16.f32 "
                    "{%0,%1,%2,%3}, {%4,%5,%6,%7}, {%8,%9}, {%0,%1,%2,%3};"
                    : "+f"(acc[mi][nj][0]), "+f"(acc[mi][nj][1]),
                      "+f"(acc[mi][nj][2]), "+f"(acc[mi][nj][3])
                    : "r"(ra[mi][0]), "r"(ra[mi][1]), "r"(ra[mi][2]),
                      "r"(ra[mi][3]), "r"(rb[nj][0]), "r"(rb[nj][1]));
            }
    }

    // Epilogue: write fp16 M[ab][o][t] directly (half2 per c-pair).
    __half* Mp = g_Mh + ab * VSLICE;
#pragma unroll
    for (int mi = 0; mi < 2; mi++) {
        int orow = o0 + mi * 16 + (lid >> 2);
#pragma unroll
        for (int nj = 0; nj < 8; nj++) {
            int t = tb + t0w + nj * 8 + (lid & 3) * 2;
            *(__half2*)(Mp + orow * TQ + t) =
                __floats2half2_rn(acc[mi][nj][0], acc[mi][nj][1]);
            *(__half2*)(Mp + (orow + 8) * TQ + t) =
                __floats2half2_rn(acc[mi][nj][2], acc[mi][nj][3]);
        }
    }
}

// ---------------------------------------------------------------------------
// K3: output transform + bias. 2 t per thread (half2 loads, float2 math).
// thread -> (n, o, p, q-pair). 524288 threads.
// ---------------------------------------------------------------------------
__global__ __launch_bounds__(256)
void k_output_transform(const float* __restrict__ bias,
                        float* __restrict__ y) {
    int tid = blockIdx.x * blockDim.x + threadIdx.x;
    int q2 = tid & 15;             // q pair index (q = 2*q2, 2*q2+1)
    int p  = (tid >> 4) & 31;
    int o  = (tid >> 9) & 63;
    int n  = tid >> 15;

    int t = (n << 10) + (p << 5) + (q2 << 1);
    int base = o * TQ + t;

    // u[x][b] = sum_a AT[x][a] * m[a][b], streamed over b (float2 lanes = 2 t)
    float2 u[4][6];
#pragma unroll
    for (int b = 0; b < 6; b++) {
        float2 m[6];
#pragma unroll
        for (int a = 0; a < 6; a++)
            m[a] = __half22float2(
                *(const __half2*)(g_Mh + (a * 6 + b) * VSLICE + base));
        u[0][b].x = m[0].x + m[1].x + m[2].x + m[3].x + m[4].x;
        u[0][b].y = m[0].y + m[1].y + m[2].y + m[3].y + m[4].y;
        u[1][b].x = m[1].x - m[2].x + 2.f * (m[3].x - m[4].x);
        u[1][b].y = m[1].y - m[2].y + 2.f * (m[3].y - m[4].y);
        u[2][b].x = m[1].x + m[2].x + 4.f * (m[3].x + m[4].x);
        u[2][b].y = m[1].y + m[2].y + 4.f * (m[3].y + m[4].y);
        u[3][b].x = m[1].x - m[2].x + 8.f * (m[3].x - m[4].x) + m[5].x;
        u[3][b].y = m[1].y - m[2].y + 8.f * (m[3].y - m[4].y) + m[5].y;
    }

    float bv = bias[o];
    // output: rows p*4+x, cols q2*8 .. q2*8+7 (two adjacent 4-pixel groups)
    float* yp = y + (((size_t)n * CH + o) << 14) + (p * 4) * 128 + q2 * 8;
#pragma unroll
    for (int xx = 0; xx < 4; xx++) {
        float2 m0 = u[xx][0], m1 = u[xx][1], m2 = u[xx][2];
        float2 m3 = u[xx][3], m4 = u[xx][4], m5 = u[xx][5];
        float4 v0, v1;
        v0.x = m0.x + m1.x + m2.x + m3.x + m4.x + bv;
        v0.y = m1.x - m2.x + 2.f * (m3.x - m4.x) + bv;
        v0.z = m1.x + m2.x + 4.f * (m3.x + m4.x) + bv;
        v0.w = m1.x - m2.x + 8.f * (m3.x - m4.x) + m5.x + bv;
        v1.x = m0.y + m1.y + m2.y + m3.y + m4.y + bv;
        v1.y = m1.y - m2.y + 2.f * (m3.y - m4.y) + bv;
        v1.z = m1.y + m2.y + 4.f * (m3.y + m4.y) + bv;
        v1.w = m1.y - m2.y + 8.f * (m3.y - m4.y) + m5.y + bv;
        *(float4*)(yp + xx * 128) = v0;
        *(float4*)(yp + xx * 128 + 4) = v1;
    }
}

// ---------------------------------------------------------------------------
extern "C" void kernel_launch(void* const* d_in, const int* in_sizes, int n_in,
                              void* d_out, int out_size) {
    const float* x    = (const float*)d_in[0];
    const float* w    = (const float*)d_in[1];
    const float* bias = (const float*)d_in[2];
    float* y = (float*)d_out;

    k_wreorder<<<(ABN * CH * 32 + 255) / 256, 256>>>(w);
    k_input_transform<<<4096, 256>>>(x);
    dim3 g2(TQ / 256, ABN);
    k_gemm_hmma<<<g2, 256>>>();
    k_output_transform<<<2048, 256>>>(bias, y);
}

// round 8
// speedup vs baseline: 1.5052x; 1.0878x over previous
#include <cuda_runtime.h>
#include <cuda_fp16.h>
#include <cstdint>

// Winograd F(4x4,3x3): N=16, Cin=Cout=64, H=W=128, pad=1, nt=32, T=16384.
// Round 8: r7 + coalesced K2 epilogue (smem-staged M writes).
//
//   K0: weight (o,i,ab) fp32 -> g_Wh[ab][o][i] fp16 (half2-coalesced writes)
//   K1: input transform x -> g_Vh[ab][i][t] fp16   (t = n*1024 + p*32 + q)
//   K2: HMMA: M[ab][o][t] = sum_i W[o][i] * V[i][t] -> g_Mh fp16
//       (acc -> smem fp16 staging -> full-row uint4 stores)
//   K3: output transform, 2 t per thread via half2, + bias -> y fp32

#define TQ 16384
#define CH 64
#define ABN 36
#define VSLICE (CH * TQ)

__device__ __half g_Vh[ABN * CH * TQ];   // 75.5 MB
__device__ __half g_Mh[ABN * CH * TQ];   // 75.5 MB
__device__ __half g_Wh[ABN * CH * CH];

__device__ __forceinline__ uint32_t smem_u32(const void* p) {
    uint32_t a;
    asm("{ .reg .u64 t; cvta.to.shared.u64 t, %1; cvt.u32.u64 %0, t; }"
        : "=r"(a) : "l"(p));
    return a;
}

// ---------------------------------------------------------------------------
// K0: weight reorder. src w[o][i][ab] fp32 -> g_Wh[ab][o][i] fp16.
// ---------------------------------------------------------------------------
__global__ void k_wreorder(const float* __restrict__ w) {
    int tid = blockIdx.x * blockDim.x + threadIdx.x;
    if (tid >= ABN * CH * 32) return;
    int i2 = tid & 31;
    int o  = (tid >> 5) & 63;
    int ab = tid >> 11;
    float a0 = w[(o * 64 + i2 * 2) * ABN + ab];
    float a1 = w[(o * 64 + i2 * 2 + 1) * ABN + ab];
    *(__half2*)(g_Wh + ab * (CH * CH) + o * CH + i2 * 2) =
        __floats2half2_rn(a0, a1);
}

// ---------------------------------------------------------------------------
// K1: input transform -> g_Vh[ab][c][t] fp16
// ---------------------------------------------------------------------------
__device__ __forceinline__ void bt_apply(const float d0, const float d1,
                                         const float d2, const float d3,
                                         const float d4, const float d5,
                                         float* out) {
    out[0] = 4.f * d0 - 5.f * d2 + d4;
    out[1] = -4.f * (d1 + d2) + d3 + d4;
    out[2] = 4.f * (d1 - d2) - d3 + d4;
    out[3] = -2.f * d1 - d2 + 2.f * d3 + d4;
    out[4] = 2.f * d1 - d2 - 2.f * d3 + d4;
    out[5] = 4.f * d1 - 5.f * d3 + d5;
}

__global__ __launch_bounds__(256)
void k_input_transform(const float* __restrict__ x) {
    int tid = blockIdx.x * blockDim.x + threadIdx.x;
    int q = tid & 31;
    int p = (tid >> 5) & 31;
    int c = (tid >> 10) & 63;
    int n = tid >> 16;

    const float* xp = x + (((long)n * CH + c) << 14);
    int r0 = p * 4 - 1;
    int c0 = q * 4 - 1;

    float d[6][6];
#pragma unroll
    for (int i = 0; i < 6; i++) {
        int r = r0 + i;
        bool rv = (r >= 0) && (r < 128);
        const float* row = xp + r * 128;
#pragma unroll
        for (int j = 0; j < 6; j++) {
            int cc = c0 + j;
            d[i][j] = (rv && cc >= 0 && cc < 128) ? row[cc] : 0.f;
        }
    }

    float wrow[6][6];
#pragma unroll
    for (int j = 0; j < 6; j++) {
        float t[6];
        bt_apply(d[0][j], d[1][j], d[2][j], d[3][j], d[4][j], d[5][j], t);
#pragma unroll
        for (int a = 0; a < 6; a++) wrow[a][j] = t[a];
    }

    int t = (n << 10) + (p << 5) + q;
    int base = c * TQ + t;
#pragma unroll
    for (int a = 0; a < 6; a++) {
        float v[6];
        bt_apply(wrow[a][0], wrow[a][1], wrow[a][2], wrow[a][3], wrow[a][4],
                 wrow[a][5], v);
#pragma unroll
        for (int b = 0; b < 6; b++) {
            g_Vh[(a * 6 + b) * VSLICE + base] = __float2half_rn(v[b]);
        }
    }
}

// ---------------------------------------------------------------------------
// K2: HMMA GEMM. grid = (TQ/256, 36), block = 256 (8 warps).
// CTA tile: o=64, t=256, K=64 (resident).
// Warp tile: 32(o) x 64(t): 2 m16 x 8 n8 mma fragments, 4 k16 steps.
// Epilogue: acc -> Ms (reuses Vs smem) -> full-row coalesced uint4 stores.
// ---------------------------------------------------------------------------
__global__ __launch_bounds__(256, 2)
void k_gemm_hmma() {
    __shared__ __half Ws[64][72];    // [o][i], +8 pad
    __shared__ __half Vs[64][264];   // [i][t], +8 pad; reused as Ms[64][264]

    const int tid = threadIdx.x;
    const int wid = tid >> 5;
    const int lid = tid & 31;
    const int ab = blockIdx.y;
    const int tb = blockIdx.x * 256;

    // Load W tile: 64x64 fp16 = 512 uint4.
    {
        const uint4* Wp = (const uint4*)(g_Wh + ab * (CH * CH));
#pragma unroll
        for (int it = 0; it < 2; it++) {
            int idx = tid + it * 256;
            int r = idx >> 3, c = idx & 7;
            *(uint4*)&Ws[r][c * 8] = Wp[idx];
        }
    }
    // Load V tile: 64 rows x 256 t fp16 = 2048 uint4.
    {
        const __half* Vp = g_Vh + ab * VSLICE + tb;
#pragma unroll
        for (int it = 0; it < 8; it++) {
            int idx = tid + it * 256;
            int r = idx >> 5, c = idx & 31;
            *(uint4*)&Vs[r][c * 8] =
                *(const uint4*)(Vp + (size_t)r * TQ + c * 8);
        }
    }
    __syncthreads();

    const int o0  = (wid & 1) * 32;
    const int t0w = (wid >> 1) * 64;

    float acc[2][8][4];
#pragma unroll
    for (int mi = 0; mi < 2; mi++)
#pragma unroll
        for (int nj = 0; nj < 8; nj++)
#pragma unroll
            for (int r = 0; r < 4; r++) acc[mi][nj][r] = 0.f;

#pragma unroll
    for (int ks = 0; ks < 4; ks++) {
        const int k0 = ks * 16;

        uint32_t ra[2][4];
#pragma unroll
        for (int mi = 0; mi < 2; mi++) {
            int row = o0 + mi * 16 + (lid & 7) + ((lid >> 3) & 1) * 8;
            int col = k0 + (lid >> 4) * 8;
            uint32_t addr = smem_u32(&Ws[row][col]);
            asm volatile(
                "ldmatrix.sync.aligned.m8n8.x4.shared.b16 {%0,%1,%2,%3}, [%4];"
                : "=r"(ra[mi][0]), "=r"(ra[mi][1]), "=r"(ra[mi][2]),
                  "=r"(ra[mi][3])
                : "r"(addr));
        }
        uint32_t rb[8][2];
#pragma unroll
        for (int njp = 0; njp < 4; njp++) {
            int row = k0 + (lid & 7) + ((lid >> 3) & 1) * 8;
            int col = t0w + njp * 16 + (lid >> 4) * 8;
            uint32_t addr = smem_u32(&Vs[row][col]);
            uint32_t r0, r1, r2, r3;
            asm volatile(
                "ldmatrix.sync.aligned.m8n8.x4.trans.shared.b16 {%0,%1,%2,%3}, [%4];"
                : "=r"(r0), "=r"(r1), "=r"(r2), "=r"(r3)
                : "r"(addr));
            rb[njp * 2][0] = r0; rb[njp * 2][1] = r1;
            rb[njp * 2 + 1][0] = r2; rb[njp * 2 + 1][1] = r3;
        }

#pragma unroll
        for (int mi = 0; mi < 2; mi++)
#pragma unroll
            for (int nj = 0; nj < 8; nj++) {
                asm volatile(
                    "mma.sync.aligned.m16n8k16.row.col.f32.f16.f16.f32 "
                    "{%0,%1,%2,%3}, {%4,%5,%6,%7}, {%8,%9}, {%0,%1,%2,%3};"
                    : "+f"(acc[mi][nj][0]), "+f"(acc[mi][nj][1]),
                      "+f"(acc[mi][nj][2]), "+f"(acc[mi][nj][3])
                    : "r"(ra[mi][0]), "r"(ra[mi][1]), "r"(ra[mi][2]),
                      "r"(ra[mi][3]), "r"(rb[nj][0]), "r"(rb[nj][1]));
            }
    }

    // All warps finished reading Vs -> safe to reuse as Ms staging.
    __syncthreads();
    __half (*Ms)[264] = (__half (*)[264])Vs;

    // Stage acc as fp16. Per store instruction: 8 rows x 4 word-cols,
    // banks (4*(lid>>2) + (lid&3)) all distinct -> conflict-free.
#pragma unroll
    for (int mi = 0; mi < 2; mi++) {
        int orow = o0 + mi * 16 + (lid >> 2);
#pragma unroll
        for (int nj = 0; nj < 8; nj++) {
            int tl = t0w + nj * 8 + (lid & 3) * 2;
            *(__half2*)&Ms[orow][tl] =
                __floats2half2_rn(acc[mi][nj][0], acc[mi][nj][1]);
            *(__half2*)&Ms[orow + 8][tl] =
                __floats2half2_rn(acc[mi][nj][2], acc[mi][nj][3]);
        }
    }
    __syncthreads();

    // Coalesced out: one warp per row, lane writes uint4 (8 halves);
    // 32 lanes cover the full 512B row. 8 passes x 8 warps = 64 rows.
    __half* Mp = g_Mh + ab * VSLICE + tb;
#pragma unroll
    for (int pass = 0; pass < 8; pass++) {
        int row = pass * 8 + wid;
        *(uint4*)(Mp + (size_t)row * TQ + lid * 8) =
            *(const uint4*)&Ms[row][lid * 8];
    }
}

// ---------------------------------------------------------------------------
// K3: output transform + bias. 2 t per thread (half2 loads, float2 math).
// ---------------------------------------------------------------------------
__global__ __launch_bounds__(256)
void k_output_transform(const float* __restrict__ bias,
                        float* __restrict__ y) {
    int tid = blockIdx.x * blockDim.x + threadIdx.x;
    int q2 = tid & 15;
    int p  = (tid >> 4) & 31;
    int o  = (tid >> 9) & 63;
    int n  = tid >> 15;

    int t = (n << 10) + (p << 5) + (q2 << 1);
    int base = o * TQ + t;

    float2 u[4][6];
#pragma unroll
    for (int b = 0; b < 6; b++) {
        float2 m[6];
#pragma unroll
        for (int a = 0; a < 6; a++)
            m[a] = __half22float2(
                *(const __half2*)(g_Mh + (a * 6 + b) * VSLICE + base));
        u[0][b].x = m[0].x + m[1].x + m[2].x + m[3].x + m[4].x;
        u[0][b].y = m[0].y + m[1].y + m[2].y + m[3].y + m[4].y;
        u[1][b].x = m[1].x - m[2].x + 2.f * (m[3].x - m[4].x);
        u[1][b].y = m[1].y - m[2].y + 2.f * (m[3].y - m[4].y);
        u[2][b].x = m[1].x + m[2].x + 4.f * (m[3].x + m[4].x);
        u[2][b].y = m[1].y + m[2].y + 4.f * (m[3].y + m[4].y);
        u[3][b].x = m[1].x - m[2].x + 8.f * (m[3].x - m[4].x) + m[5].x;
        u[3][b].y = m[1].y - m[2].y + 8.f * (m[3].y - m[4].y) + m[5].y;
    }

    float bv = bias[o];
    float* yp = y + (((size_t)n * CH + o) << 14) + (p * 4) * 128 + q2 * 8;
#pragma unroll
    for (int xx = 0; xx < 4; xx++) {
        float2 m0 = u[xx][0], m1 = u[xx][1], m2 = u[xx][2];
        float2 m3 = u[xx][3], m4 = u[xx][4], m5 = u[xx][5];
        float4 v0, v1;
        v0.x = m0.x + m1.x + m2.x + m3.x + m4.x + bv;
        v0.y = m1.x - m2.x + 2.f * (m3.x - m4.x) + bv;
        v0.z = m1.x + m2.x + 4.f * (m3.x + m4.x) + bv;
        v0.w = m1.x - m2.x + 8.f * (m3.x - m4.x) + m5.x + bv;
        v1.x = m0.y + m1.y + m2.y + m3.y + m4.y + bv;
        v1.y = m1.y - m2.y + 2.f * (m3.y - m4.y) + bv;
        v1.z = m1.y + m2.y + 4.f * (m3.y + m4.y) + bv;
        v1.w = m1.y - m2.y + 8.f * (m3.y - m4.y) + m5.y + bv;
        *(float4*)(yp + xx * 128) = v0;
        *(float4*)(yp + xx * 128 + 4) = v1;
    }
}

// ---------------------------------------------------------------------------
extern "C" void kernel_launch(void* const* d_in, const int* in_sizes, int n_in,
                              void* d_out, int out_size) {
    const float* x    = (const float*)d_in[0];
    const float* w    = (const float*)d_in[1];
    const float* bias = (const float*)d_in[2];
    float* y = (float*)d_out;

    k_wreorder<<<(ABN * CH * 32 + 255) / 256, 256>>>(w);
    k_input_transform<<<4096, 256>>>(x);
    dim3 g2(TQ / 256, ABN);
    k_gemm_hmma<<<g2, 256>>>();
    k_output_transform<<<2048, 256>>>(bias, y);
}